// round 7
// baseline (speedup 1.0000x reference)
#include <cuda_runtime.h>

// Problem constants
#define B_  4
#define C_  16
#define H_  64
#define W_  64
#define F_  32
#define CC  4            // channels per smem chunk (4 chunks)
#define NR  6            // pair-row slots per channel (r = 0..5)
#define XPITCH 68        // doubles per slot row: logical cols -1..64 at phys 0..65, +2 pad
#define SLOT (NR * XPITCH)
#define NTHREADS 128

typedef unsigned long long ull;

__device__ __forceinline__ float frcp(float q) {
    float r;
    asm("rcp.approx.f32 %0, %1;" : "=f"(r) : "f"(q));
    return r;
}
__device__ __forceinline__ ull pack2(float lo, float hi) {
    ull r;
    asm("mov.b64 %0, {%1, %2};" : "=l"(r) : "f"(lo), "f"(hi));
    return r;
}
__device__ __forceinline__ void unpack2(ull v, float& lo, float& hi) {
    asm("mov.b64 {%0, %1}, %2;" : "=f"(lo), "=f"(hi) : "l"(v));
}
__device__ __forceinline__ ull fma2(ull a, ull b, ull c) {
    ull d;
    asm("fma.rn.f32x2 %0, %1, %2, %3;" : "=l"(d) : "l"(a), "l"(b), "l"(c));
    return d;
}
__device__ __forceinline__ ull mul2(ull a, ull b) {
    ull d;
    asm("mul.rn.f32x2 %0, %1, %2;" : "=l"(d) : "l"(a), "l"(b));
    return d;
}

// One packed rational tap: acc += P(xp) * rcp(1+|S(xp)*xp|) per lane.
// abs is a free operand-modifier on the scalar FADD; the lane extracts/inserts
// around MUFU are allocator-elidable (no cross-pair shuffles).
__device__ __forceinline__ void eval_tap(ull xp,
                                         ull A5, ull A4, ull A3, ull A2, ull A1, ull A0,
                                         ull B4, ull B3, ull B2, ull B1,
                                         ull& acc)
{
    ull P = fma2(A5, xp, A4);
    P = fma2(P, xp, A3);
    P = fma2(P, xp, A2);
    P = fma2(P, xp, A1);
    P = fma2(P, xp, A0);
    ull S = fma2(B4, xp, B3);
    S = fma2(S, xp, B2);
    S = fma2(S, xp, B1);
    const ull Sx = mul2(S, xp);
    float s0, s1;
    unpack2(Sx, s0, s1);
    const float r0 = frcp(1.0f + fabsf(s0));
    const float r1 = frcp(1.0f + fabsf(s1));
    acc = fma2(P, pack2(r0, r1), acc);
}

__global__ __launch_bounds__(NTHREADS, 7)
void kaconv_kernel(const float* __restrict__ x,
                   const float* __restrict__ nums,
                   const float* __restrict__ denoms,
                   float* __restrict__ out)
{
    // Coeffs duplicated into f32x2 double slots, Horner order per (c,k):
    // [a5 a4 | a3 a2 | a1 a0 | b4 b3 | b2 b1]  (5 x double2)
    __shared__ __align__(16) double scf[C_ * 9 * 10];   // 11520 B
    // Pre-packed row-pair tile: slot (c, r, p) = pack(x[gy0+r-1][p-1], x[gy0+r+3][p-1])
    __shared__ double spx[CC * SLOT];                    // 13056 B  (total 24576 B)

    const int tx  = threadIdx.x;        // 0..31
    const int ty  = threadIdx.y;        // 0..3
    const int tid = ty * 32 + tx;
    const int f   = blockIdx.z & (F_ - 1);
    const int b   = blockIdx.z >> 5;
    const int gy0 = blockIdx.y * 8;     // 8 output rows per block, full 64-col width

    // ---- stage Pade coefficients for filter f (144 (c,k) slots) ----
    for (int i = tid; i < C_ * 9; i += NTHREADS) {
        const float* np = nums   + (size_t)f * (C_ * 9 * 6) + i * 6;
        const float* dp = denoms + (size_t)f * (C_ * 9 * 4) + i * 4;
        double* dst = scf + i * 10;
        float a0 = np[0], a1 = np[1], a2 = np[2], a3 = np[3], a4 = np[4], a5 = np[5];
        float b1 = dp[0], b2 = dp[1], b3 = dp[2], b4 = dp[3];
        dst[0] = __longlong_as_double((long long)pack2(a5, a5));
        dst[1] = __longlong_as_double((long long)pack2(a4, a4));
        dst[2] = __longlong_as_double((long long)pack2(a3, a3));
        dst[3] = __longlong_as_double((long long)pack2(a2, a2));
        dst[4] = __longlong_as_double((long long)pack2(a1, a1));
        dst[5] = __longlong_as_double((long long)pack2(a0, a0));
        dst[6] = __longlong_as_double((long long)pack2(b4, b4));
        dst[7] = __longlong_as_double((long long)pack2(b3, b3));
        dst[8] = __longlong_as_double((long long)pack2(b2, b2));
        dst[9] = __longlong_as_double((long long)pack2(b1, b1));
    }

    // Thread owns: row pair (gy0+ty, gy0+ty+4), columns tx and tx+32.
    ull accL = 0ull;   // col tx
    ull accR = 0ull;   // col tx+32

    // ---- four channel chunks of 4 ----
    for (int chunk = 0; chunk < 4; ++chunk) {
        const int ch0 = chunk * CC;

        __syncthreads();   // protect prior-iter tile reads (and coeff writes @chunk 0)

        // stage pre-packed pair tile
        const float* xb = x + ((size_t)(b * C_ + ch0)) * (H_ * W_);
        for (int i = tid; i < CC * SLOT; i += NTHREADS) {
            const int c   = i / SLOT;
            const int rem = i - c * SLOT;
            const int r   = rem / XPITCH;
            const int p   = rem - r * XPITCH;
            const int gya = gy0 + r - 1;     // lo lane row
            const int gyb = gya + 4;         // hi lane row
            const int gx  = p - 1;           // logical col
            const float* xc = xb + c * (H_ * W_);
            float va = 0.f, vb = 0.f;
            if ((unsigned)gx < W_) {
                if ((unsigned)gya < H_) va = xc[gya * W_ + gx];
                if ((unsigned)gyb < H_) vb = xc[gyb * W_ + gx];
            }
            spx[i] = __longlong_as_double((long long)pack2(va, vb));
        }

        __syncthreads();

        // ---- rational conv accumulate ----
        #pragma unroll 1
        for (int c = 0; c < CC; ++c) {
            // tap (a, bb): pair slot row ty+a, phys col (tx + bb) / (tx + 32 + bb)
            const double*  xc = spx + c * SLOT + ty * XPITCH + tx;
            const double2* cp = (const double2*)(scf + (ch0 + c) * 90);
            #pragma unroll
            for (int a = 0; a < 3; ++a) {
                #pragma unroll
                for (int bb = 0; bb < 3; ++bb) {
                    const int k = a * 3 + bb;
                    const double2 d0 = cp[k * 5 + 0];   // a5 a4
                    const double2 d1 = cp[k * 5 + 1];   // a3 a2
                    const double2 d2 = cp[k * 5 + 2];   // a1 a0
                    const double2 d3 = cp[k * 5 + 3];   // b4 b3
                    const double2 d4 = cp[k * 5 + 4];   // b2 b1
                    const ull A5 = __double_as_longlong(d0.x), A4 = __double_as_longlong(d0.y);
                    const ull A3 = __double_as_longlong(d1.x), A2 = __double_as_longlong(d1.y);
                    const ull A1 = __double_as_longlong(d2.x), A0 = __double_as_longlong(d2.y);
                    const ull B4 = __double_as_longlong(d3.x), B3 = __double_as_longlong(d3.y);
                    const ull B2 = __double_as_longlong(d4.x), B1 = __double_as_longlong(d4.y);

                    const ull xpL = __double_as_longlong(xc[a * XPITCH + bb]);
                    const ull xpR = __double_as_longlong(xc[a * XPITCH + bb + 32]);
                    eval_tap(xpL, A5, A4, A3, A2, A1, A0, B4, B3, B2, B1, accL);
                    eval_tap(xpR, A5, A4, A3, A2, A1, A0, B4, B3, B2, B1, accR);
                }
            }
        }
    }

    // ---- write (B,F,H,W): 4 scalars, lane-consecutive -> coalesced ----
    float oL0, oL1, oR0, oR1;
    unpack2(accL, oL0, oL1);
    unpack2(accR, oR0, oR1);
    float* op = out + ((size_t)blockIdx.z * H_ + gy0 + ty) * W_ + tx;
    op[0]                      = oL0;
    op[32]                     = oR0;
    op[(size_t)4 * W_]         = oL1;
    op[(size_t)4 * W_ + 32]    = oR1;
}

extern "C" void kernel_launch(void* const* d_in, const int* in_sizes, int n_in,
                              void* d_out, int out_size) {
    const float* x      = (const float*)d_in[0];
    const float* nums   = (const float*)d_in[1];
    const float* denoms = (const float*)d_in[2];
    float* out = (float*)d_out;

    dim3 grid(1, H_ / 8, B_ * F_);   // 1 x 8 x 128 = 1024 blocks, single wave @ occ 7
    dim3 block(32, 4);
    kaconv_kernel<<<grid, block>>>(x, nums, denoms, out);
}